// round 1
// baseline (speedup 1.0000x reference)
#include <cuda_runtime.h>
#include <math.h>

#define SS 4096
#define BB 64
#define HH 512
#define SPLITS 8
#define CHUNK (SS / SPLITS)   // 512 rows per (b, split)
#define NWARP 16              // 512 threads

// Scratch (no allocation allowed in kernel_launch)
__device__ float g_u[BB * HH];                     // u[b,h] = sum_i W_a[i,h] * h_t[b,i]
__device__ float g_pm[BB * SPLITS];                // partial max
__device__ float g_pl[BB * SPLITS];                // partial sum-of-exp
__device__ float g_pacc[BB * SPLITS * HH];         // partial weighted accumulators

// ---------------------------------------------------------------------------
// K1: u[b,j] = sum_i W_a[i*H + j] * h_t[b*H + i]   (coalesced over j)
// ---------------------------------------------------------------------------
__global__ void __launch_bounds__(HH) k1_proj(const float* __restrict__ W_a,
                                              const float* __restrict__ h_t) {
    __shared__ float sh[HH];
    const int b = blockIdx.x;
    const int j = threadIdx.x;
    sh[j] = h_t[b * HH + j];
    __syncthreads();
    float acc = 0.f;
#pragma unroll 8
    for (int i = 0; i < HH; i++) acc += W_a[i * HH + j] * sh[i];
    g_u[b * HH + j] = acc;
}

// ---------------------------------------------------------------------------
// K2: single pass over encoder_hidden_states with online softmax.
// grid = (SPLITS, B), block = 512 threads = 16 warps.
// Each warp keeps its own running (m, l, acc[512]) — acc fully in registers
// (4x float4 per lane). Block-combine into per-(b,split) partials.
// ---------------------------------------------------------------------------
__global__ void __launch_bounds__(512) k2_flash(const float* __restrict__ hs,
                                                const int* __restrict__ mask) {
    const int split = blockIdx.x;
    const int b     = blockIdx.y;
    const int warp  = threadIdx.x >> 5;
    const int lane  = threadIdx.x & 31;

    // u[b] slice for this lane (h = 4*(lane+32k) .. +3)
    float4 u4[4];
    const float4* up = reinterpret_cast<const float4*>(g_u + b * HH);
#pragma unroll
    for (int k = 0; k < 4; k++) u4[k] = up[lane + 32 * k];

    float m = -1e30f, l = 0.f;
    float4 acc[4];
#pragma unroll
    for (int k = 0; k < 4; k++) acc[k] = make_float4(0.f, 0.f, 0.f, 0.f);

    const int s_base = split * CHUNK + warp;
    for (int r = 0; r < CHUNK / NWARP; r++) {
        const int s = s_base + r * NWARP;
        const float4* xp =
            reinterpret_cast<const float4*>(hs + ((size_t)s * BB + b) * HH);
        float4 x[4];
#pragma unroll
        for (int k = 0; k < 4; k++) x[k] = xp[lane + 32 * k];

        float dot = 0.f;
#pragma unroll
        for (int k = 0; k < 4; k++)
            dot += x[k].x * u4[k].x + x[k].y * u4[k].y +
                   x[k].z * u4[k].z + x[k].w * u4[k].w;
#pragma unroll
        for (int off = 16; off; off >>= 1)
            dot += __shfl_xor_sync(0xffffffffu, dot, off);

        float score = dot;
        if (mask[b * SS + s] == 0) score = -1e30f;

        if (score <= m) {                    // common path: no rescale
            const float p = __expf(score - m);
            l += p;
#pragma unroll
            for (int k = 0; k < 4; k++) {
                acc[k].x += p * x[k].x; acc[k].y += p * x[k].y;
                acc[k].z += p * x[k].z; acc[k].w += p * x[k].w;
            }
        } else {                             // new max: rescale old state
            const float f = __expf(m - score);
            l = l * f + 1.f;
#pragma unroll
            for (int k = 0; k < 4; k++) {
                acc[k].x = acc[k].x * f + x[k].x;
                acc[k].y = acc[k].y * f + x[k].y;
                acc[k].z = acc[k].z * f + x[k].z;
                acc[k].w = acc[k].w * f + x[k].w;
            }
            m = score;
        }
    }

    // ---- block combine: 16 warp states -> one partial ----
    __shared__ float sm[NWARP];
    __shared__ float sl[NWARP];
    __shared__ float sacc[NWARP][HH];   // 32 KB

    if (lane == 0) { sm[warp] = m; sl[warp] = l; }
    float4* srow = reinterpret_cast<float4*>(sacc[warp]);
#pragma unroll
    for (int k = 0; k < 4; k++) srow[lane + 32 * k] = acc[k];
    __syncthreads();

    const int h = threadIdx.x;            // 0..511
    float M = -1e30f;
#pragma unroll
    for (int w = 0; w < NWARP; w++) M = fmaxf(M, sm[w]);
    float L = 0.f, A = 0.f;
#pragma unroll
    for (int w = 0; w < NWARP; w++) {
        const float wgt = __expf(sm[w] - M);
        L += wgt * sl[w];
        A += wgt * sacc[w][h];
    }
    const int pidx = b * SPLITS + split;
    g_pacc[(size_t)pidx * HH + h] = A;
    if (h == 0) { g_pm[pidx] = M; g_pl[pidx] = L; }
}

// ---------------------------------------------------------------------------
// K3: combine SPLITS partials -> c_t, then out = tanh([c_t, h_t] @ W_r^T + b_r)
// grid = B, block = 512.
// ---------------------------------------------------------------------------
__global__ void __launch_bounds__(512) k3_final(const float* __restrict__ h_t,
                                                const float* __restrict__ W_r,
                                                const float* __restrict__ b_r,
                                                float* __restrict__ out) {
    const int b = blockIdx.x;
    __shared__ float cat[2 * HH];

    const int h = threadIdx.x;
    float M = -1e30f;
#pragma unroll
    for (int s = 0; s < SPLITS; s++) M = fmaxf(M, g_pm[b * SPLITS + s]);
    float L = 0.f, A = 0.f;
#pragma unroll
    for (int s = 0; s < SPLITS; s++) {
        const float wgt = __expf(g_pm[b * SPLITS + s] - M);
        L += wgt * g_pl[b * SPLITS + s];
        A += wgt * g_pacc[(size_t)(b * SPLITS + s) * HH + h];
    }
    cat[h]      = A / L;                   // c_t[b,h]
    cat[HH + h] = h_t[b * HH + h];
    __syncthreads();

    const int warp = h >> 5, lane = h & 31;
    const float4* catv = reinterpret_cast<const float4*>(cat);
    for (int o = warp; o < HH; o += NWARP) {
        const float4* wr =
            reinterpret_cast<const float4*>(W_r + (size_t)o * (2 * HH));
        float dot = 0.f;
#pragma unroll
        for (int k = 0; k < 8; k++) {
            const float4 w4 = wr[lane + 32 * k];
            const float4 c4 = catv[lane + 32 * k];
            dot += w4.x * c4.x + w4.y * c4.y + w4.z * c4.z + w4.w * c4.w;
        }
#pragma unroll
        for (int off = 16; off; off >>= 1)
            dot += __shfl_xor_sync(0xffffffffu, dot, off);
        if (lane == 0) out[b * HH + o] = tanhf(dot + b_r[o]);
    }
}

// ---------------------------------------------------------------------------
extern "C" void kernel_launch(void* const* d_in, const int* in_sizes, int n_in,
                              void* d_out, int out_size) {
    const float* hs   = (const float*)d_in[0];   // [S,B,H]
    const float* h_t  = (const float*)d_in[1];   // [B,H]
    const int*   mask = (const int*)  d_in[2];   // [B,S]
    const float* W_a  = (const float*)d_in[3];   // [H,H]
    // d_in[4] = b_a : mathematically cancels in softmax (per-b constant)
    const float* W_r  = (const float*)d_in[5];   // [H,2H]
    const float* b_r  = (const float*)d_in[6];   // [H]
    float* out = (float*)d_out;                  // [B,H]

    k1_proj<<<BB, HH>>>(W_a, h_t);
    k2_flash<<<dim3(SPLITS, BB), 512>>>(hs, mask);
    k3_final<<<BB, 512>>>(h_t, W_r, b_r, out);
}

// round 2
// speedup vs baseline: 1.0663x; 1.0663x over previous
#include <cuda_runtime.h>
#include <math.h>

#define SS 4096
#define BB 64
#define HH 512
#define SPL 16
#define CH (SS / SPL)   // 256 rows per (b, split)

// Scratch (device globals — no allocation allowed)
__device__ float g_u[BB * HH];               // u[b,j] = sum_i W_a[i,j] h_t[b,i]
__device__ float g_ct[BB * HH];              // c_t
__device__ float g_pm[BB * SPL];             // partial max
__device__ float g_pl[BB * SPL];             // partial sum-exp
__device__ float g_pacc[BB * SPL * HH];      // partial weighted accumulators

// ---------------------------------------------------------------------------
// K1: u[b,j] = sum_i W_a[i,j] * h_t[b,i].  W_a read EXACTLY ONCE total.
// grid = 32 CTAs (16 j-columns each), block = 512 (warp = j-col, lane = b, 2 b/thread)
// ---------------------------------------------------------------------------
__global__ void __launch_bounds__(512) k1_proj(const float* __restrict__ W_a,
                                               const float* __restrict__ h_t) {
    __shared__ float h_sh[64][65];   // [i_local][b], padded
    __shared__ float W_sh[64][16];   // [i_local][j_local]
    __shared__ float u_sh[16][65];   // staging for coalesced write
    const int t = threadIdx.x;
    const int jl = t >> 5, lane = t & 31;
    const int j0 = blockIdx.x * 16;

    float acc0 = 0.f, acc1 = 0.f;
    for (int c = 0; c < 8; c++) {
        const int ibase = c * 64;
        for (int idx = t; idx < 64 * 64; idx += 512) {
            const int bb = idx >> 6, il = idx & 63;
            h_sh[il][bb] = h_t[bb * HH + ibase + il];
        }
        for (int idx = t; idx < 64 * 16; idx += 512) {
            const int il = idx >> 4, jj = idx & 15;
            W_sh[il][jj] = W_a[(ibase + il) * HH + j0 + jj];
        }
        __syncthreads();
#pragma unroll 16
        for (int il = 0; il < 64; il++) {
            const float wv = W_sh[il][jl];          // warp-uniform broadcast
            acc0 += wv * h_sh[il][lane];
            acc1 += wv * h_sh[il][lane + 32];
        }
        __syncthreads();
    }
    u_sh[jl][lane]      = acc0;
    u_sh[jl][lane + 32] = acc1;
    __syncthreads();
    for (int idx = t; idx < 1024; idx += 512) {
        const int bb = idx >> 4, jj = idx & 15;
        g_u[bb * HH + j0 + jj] = u_sh[jj][bb];
    }
}

// ---------------------------------------------------------------------------
// K2: single streaming pass with online softmax, 2 rows/iter (MLP=8/warp).
// grid = (SPL, B) = 1024 CTAs, block = 256 (8 warps). Branch-free update.
// ---------------------------------------------------------------------------
__global__ void __launch_bounds__(256) k2_flash(const float* __restrict__ hs,
                                                const int* __restrict__ mask) {
    const int split = blockIdx.x;
    const int b     = blockIdx.y;
    const int warp  = threadIdx.x >> 5;
    const int lane  = threadIdx.x & 31;

    float4 u4[4];
    const float4* up = reinterpret_cast<const float4*>(g_u + b * HH);
#pragma unroll
    for (int k = 0; k < 4; k++) u4[k] = up[lane + 32 * k];

    float m = -1e30f, l = 0.f;
    float4 acc[4];
#pragma unroll
    for (int k = 0; k < 4; k++) acc[k] = make_float4(0.f, 0.f, 0.f, 0.f);

    const int base = split * CH + warp;
    const float4* hs4 = reinterpret_cast<const float4*>(hs);

    for (int it = 0; it < CH / 16; it++) {
        const int s0 = base + it * 16;
        const int s1 = s0 + 8;
        const size_t r0 = ((size_t)s0 * BB + b) * (HH / 4);
        const size_t r1 = ((size_t)s1 * BB + b) * (HH / 4);
        float4 x0[4], x1[4];
#pragma unroll
        for (int k = 0; k < 4; k++) x0[k] = __ldcs(&hs4[r0 + lane + 32 * k]);
#pragma unroll
        for (int k = 0; k < 4; k++) x1[k] = __ldcs(&hs4[r1 + lane + 32 * k]);

        float d0 = 0.f, d1 = 0.f;
#pragma unroll
        for (int k = 0; k < 4; k++) {
            d0 += x0[k].x * u4[k].x + x0[k].y * u4[k].y +
                  x0[k].z * u4[k].z + x0[k].w * u4[k].w;
            d1 += x1[k].x * u4[k].x + x1[k].y * u4[k].y +
                  x1[k].z * u4[k].z + x1[k].w * u4[k].w;
        }
#pragma unroll
        for (int off = 16; off; off >>= 1) {
            d0 += __shfl_xor_sync(0xffffffffu, d0, off);
            d1 += __shfl_xor_sync(0xffffffffu, d1, off);
        }
        const float sv0 = mask[b * SS + s0] ? d0 : -1e30f;
        const float sv1 = mask[b * SS + s1] ? d1 : -1e30f;

        const float mn = fmaxf(m, fmaxf(sv0, sv1));
        const float f  = __expf(m   - mn);
        const float p0 = __expf(sv0 - mn);
        const float p1 = __expf(sv1 - mn);
        l = l * f + p0 + p1;
#pragma unroll
        for (int k = 0; k < 4; k++) {
            acc[k].x = acc[k].x * f + p0 * x0[k].x + p1 * x1[k].x;
            acc[k].y = acc[k].y * f + p0 * x0[k].y + p1 * x1[k].y;
            acc[k].z = acc[k].z * f + p0 * x0[k].z + p1 * x1[k].z;
            acc[k].w = acc[k].w * f + p0 * x0[k].w + p1 * x1[k].w;
        }
        m = mn;
    }

    // ---- block combine: 8 warp states -> one partial ----
    __shared__ float sm[8];
    __shared__ float sl[8];
    __shared__ float sacc[8][HH];   // 16 KB
    if (lane == 0) { sm[warp] = m; sl[warp] = l; }
    float4* srow = reinterpret_cast<float4*>(sacc[warp]);
#pragma unroll
    for (int k = 0; k < 4; k++) srow[lane + 32 * k] = acc[k];
    __syncthreads();

    float M = -1e30f;
#pragma unroll
    for (int w = 0; w < 8; w++) M = fmaxf(M, sm[w]);
    const int pidx = b * SPL + split;
    for (int h = threadIdx.x; h < HH; h += 256) {
        float L = 0.f, A = 0.f;
#pragma unroll
        for (int w = 0; w < 8; w++) {
            const float wgt = __expf(sm[w] - M);
            L += wgt * sl[w];
            A += wgt * sacc[w][h];
        }
        g_pacc[(size_t)pidx * HH + h] = A;
        if (h == 0) { g_pm[pidx] = M; g_pl[pidx] = L; }
    }
}

// ---------------------------------------------------------------------------
// K3a: combine SPL partials -> c_t
// ---------------------------------------------------------------------------
__global__ void __launch_bounds__(512) k3a_combine() {
    const int b = blockIdx.x, h = threadIdx.x;
    float M = -1e30f;
#pragma unroll
    for (int s = 0; s < SPL; s++) M = fmaxf(M, g_pm[b * SPL + s]);
    float L = 0.f, A = 0.f;
#pragma unroll
    for (int s = 0; s < SPL; s++) {
        const float wgt = __expf(g_pm[b * SPL + s] - M);
        L += wgt * g_pl[b * SPL + s];
        A += wgt * g_pacc[(size_t)(b * SPL + s) * HH + h];
    }
    g_ct[b * HH + h] = A / L;
}

// ---------------------------------------------------------------------------
// K3b: out = tanh([c_t, h_t] @ W_r^T + b_r).  W_r read exactly once.
// grid = 128 CTAs (4 o-cols each), block = 256 (ol = t>>6, b = t&63)
// ---------------------------------------------------------------------------
__global__ void __launch_bounds__(256) k3b_out(const float* __restrict__ h_t,
                                               const float* __restrict__ W_r,
                                               const float* __restrict__ b_r,
                                               float* __restrict__ out) {
    __shared__ float cat_sh[128][65];   // [k_local][b], padded
    __shared__ float W_sh[4][128];
    const int t = threadIdx.x;
    const int ol = t >> 6, b = t & 63;
    const int obase = blockIdx.x * 4;

    float acc = 0.f;
    for (int c = 0; c < 8; c++) {
        const int kbase = c * 128;
        const float* src = (kbase < HH) ? (g_ct + kbase) : (h_t + kbase - HH);
        for (int idx = t; idx < 128 * 64; idx += 256) {
            const int bb = idx >> 7, kl = idx & 127;
            cat_sh[kl][bb] = src[bb * HH + kl];
        }
        for (int idx = t; idx < 4 * 128; idx += 256) {
            const int oo = idx >> 7, kl = idx & 127;
            W_sh[oo][kl] = W_r[(size_t)(obase + oo) * (2 * HH) + kbase + kl];
        }
        __syncthreads();
#pragma unroll 16
        for (int kl = 0; kl < 128; kl++)
            acc += W_sh[ol][kl] * cat_sh[kl][b];
        __syncthreads();
    }
    out[b * HH + obase + ol] = tanhf(acc + b_r[obase + ol]);
}

// ---------------------------------------------------------------------------
extern "C" void kernel_launch(void* const* d_in, const int* in_sizes, int n_in,
                              void* d_out, int out_size) {
    const float* hs   = (const float*)d_in[0];   // [S,B,H]
    const float* h_t  = (const float*)d_in[1];   // [B,H]
    const int*   mask = (const int*)  d_in[2];   // [B,S]
    const float* W_a  = (const float*)d_in[3];   // [H,H]
    // d_in[4] = b_a : cancels in softmax (per-b constant)
    const float* W_r  = (const float*)d_in[5];   // [H,2H]
    const float* b_r  = (const float*)d_in[6];   // [H]
    float* out = (float*)d_out;                  // [B,H]

    k1_proj<<<HH / 16, 512>>>(W_a, h_t);
    k2_flash<<<dim3(SPL, BB), 256>>>(hs, mask);
    k3a_combine<<<BB, 512>>>();
    k3b_out<<<HH / 4, 256>>>(h_t, W_r, b_r, out);
}

// round 3
// speedup vs baseline: 1.2271x; 1.1508x over previous
#include <cuda_runtime.h>
#include <math.h>

#define SS 4096
#define BB 64
#define HH 512
#define SPL 16
#define CH (SS / SPL)   // 256 rows per (b, split)
#define KS 16           // split-K slices for final GEMM
#define KSL 64          // K per slice (2H / KS)

// Scratch (device globals — no allocation allowed)
__device__ float g_u[BB * HH];               // u[b,j] = sum_i W_a[i,j] h_t[b,i]
__device__ float g_ct[BB * HH];              // c_t
__device__ float g_pm[BB * SPL];             // partial max
__device__ float g_pl[BB * SPL];             // partial sum-exp
__device__ float g_pacc[BB * SPL * HH];      // partial weighted accumulators
__device__ float g_opart[KS * HH * BB];      // [ks][o][b] GEMM partials (2 MB)

// ---------------------------------------------------------------------------
// K1: u[b,j] = sum_i W_a[i,j] * h_t[b,i].  W_a read EXACTLY ONCE total.
// ---------------------------------------------------------------------------
__global__ void __launch_bounds__(512) k1_proj(const float* __restrict__ W_a,
                                               const float* __restrict__ h_t) {
    __shared__ float h_sh[64][65];
    __shared__ float W_sh[64][16];
    __shared__ float u_sh[16][65];
    const int t = threadIdx.x;
    const int jl = t >> 5, lane = t & 31;
    const int j0 = blockIdx.x * 16;

    float acc0 = 0.f, acc1 = 0.f;
    for (int c = 0; c < 8; c++) {
        const int ibase = c * 64;
        for (int idx = t; idx < 64 * 64; idx += 512) {
            const int bb = idx >> 6, il = idx & 63;
            h_sh[il][bb] = h_t[bb * HH + ibase + il];
        }
        for (int idx = t; idx < 64 * 16; idx += 512) {
            const int il = idx >> 4, jj = idx & 15;
            W_sh[il][jj] = W_a[(ibase + il) * HH + j0 + jj];
        }
        __syncthreads();
#pragma unroll 16
        for (int il = 0; il < 64; il++) {
            const float wv = W_sh[il][jl];
            acc0 += wv * h_sh[il][lane];
            acc1 += wv * h_sh[il][lane + 32];
        }
        __syncthreads();
    }
    u_sh[jl][lane]      = acc0;
    u_sh[jl][lane + 32] = acc1;
    __syncthreads();
    for (int idx = t; idx < 1024; idx += 512) {
        const int bb = idx >> 4, jj = idx & 15;
        g_u[bb * HH + j0 + jj] = u_sh[jj][bb];
    }
}

// ---------------------------------------------------------------------------
// K2: single streaming pass with online softmax, 2 rows/iter (MLP=8/warp).
// grid = (SPL, B) = 1024 CTAs, block = 256 (8 warps).
// ---------------------------------------------------------------------------
__global__ void __launch_bounds__(256) k2_flash(const float* __restrict__ hs,
                                                const int* __restrict__ mask) {
    const int split = blockIdx.x;
    const int b     = blockIdx.y;
    const int warp  = threadIdx.x >> 5;
    const int lane  = threadIdx.x & 31;

    float4 u4[4];
    const float4* up = reinterpret_cast<const float4*>(g_u + b * HH);
#pragma unroll
    for (int k = 0; k < 4; k++) u4[k] = up[lane + 32 * k];

    float m = -1e30f, l = 0.f;
    float4 acc[4];
#pragma unroll
    for (int k = 0; k < 4; k++) acc[k] = make_float4(0.f, 0.f, 0.f, 0.f);

    const int base = split * CH + warp;
    const float4* hs4 = reinterpret_cast<const float4*>(hs);

    for (int it = 0; it < CH / 16; it++) {
        const int s0 = base + it * 16;
        const int s1 = s0 + 8;
        const size_t r0 = ((size_t)s0 * BB + b) * (HH / 4);
        const size_t r1 = ((size_t)s1 * BB + b) * (HH / 4);
        float4 x0[4], x1[4];
#pragma unroll
        for (int k = 0; k < 4; k++) x0[k] = __ldcs(&hs4[r0 + lane + 32 * k]);
#pragma unroll
        for (int k = 0; k < 4; k++) x1[k] = __ldcs(&hs4[r1 + lane + 32 * k]);
        const int mk0 = mask[b * SS + s0];
        const int mk1 = mask[b * SS + s1];

        float d0 = 0.f, d1 = 0.f;
#pragma unroll
        for (int k = 0; k < 4; k++) {
            d0 += x0[k].x * u4[k].x + x0[k].y * u4[k].y +
                  x0[k].z * u4[k].z + x0[k].w * u4[k].w;
            d1 += x1[k].x * u4[k].x + x1[k].y * u4[k].y +
                  x1[k].z * u4[k].z + x1[k].w * u4[k].w;
        }
#pragma unroll
        for (int off = 16; off; off >>= 1) {
            d0 += __shfl_xor_sync(0xffffffffu, d0, off);
            d1 += __shfl_xor_sync(0xffffffffu, d1, off);
        }
        const float sv0 = mk0 ? d0 : -1e30f;
        const float sv1 = mk1 ? d1 : -1e30f;

        const float mn = fmaxf(m, fmaxf(sv0, sv1));
        const float f  = __expf(m - mn);
        float p0 = __expf(sv0 - mn);
        float p1 = __expf(sv1 - mn);
        p0 = mk0 ? p0 : 0.f;               // exact zero for masked rows
        p1 = mk1 ? p1 : 0.f;
        l = l * f + p0 + p1;
#pragma unroll
        for (int k = 0; k < 4; k++) {
            acc[k].x = acc[k].x * f + p0 * x0[k].x + p1 * x1[k].x;
            acc[k].y = acc[k].y * f + p0 * x0[k].y + p1 * x1[k].y;
            acc[k].z = acc[k].z * f + p0 * x0[k].z + p1 * x1[k].z;
            acc[k].w = acc[k].w * f + p0 * x0[k].w + p1 * x1[k].w;
        }
        m = mn;
    }

    __shared__ float sm[8];
    __shared__ float sl[8];
    __shared__ float sacc[8][HH];
    if (lane == 0) { sm[warp] = m; sl[warp] = l; }
    float4* srow = reinterpret_cast<float4*>(sacc[warp]);
#pragma unroll
    for (int k = 0; k < 4; k++) srow[lane + 32 * k] = acc[k];
    __syncthreads();

    float M = -1e30f;
#pragma unroll
    for (int w = 0; w < 8; w++) M = fmaxf(M, sm[w]);
    const int pidx = b * SPL + split;
    for (int h = threadIdx.x; h < HH; h += 256) {
        float L = 0.f, A = 0.f;
#pragma unroll
        for (int w = 0; w < 8; w++) {
            const float wgt = __expf(sm[w] - M);
            L += wgt * sl[w];
            A += wgt * sacc[w][h];
        }
        g_pacc[(size_t)pidx * HH + h] = A;
        if (h == 0) { g_pm[pidx] = M; g_pl[pidx] = L; }
    }
}

// ---------------------------------------------------------------------------
// K3a: combine SPL partials -> c_t
// ---------------------------------------------------------------------------
__global__ void __launch_bounds__(512) k3a_combine() {
    const int b = blockIdx.x, h = threadIdx.x;
    float M = -1e30f;
#pragma unroll
    for (int s = 0; s < SPL; s++) M = fmaxf(M, g_pm[b * SPL + s]);
    float L = 0.f, A = 0.f;
#pragma unroll
    for (int s = 0; s < SPL; s++) {
        const float wgt = __expf(g_pm[b * SPL + s] - M);
        L += wgt * g_pl[b * SPL + s];
        A += wgt * g_pacc[(size_t)(b * SPL + s) * HH + h];
    }
    g_ct[b * HH + h] = A / L;
}

// ---------------------------------------------------------------------------
// K3b: split-K GEMM partials: opart[ks][o][b] = sum_{k in slice} W_r[o,k]*cat[b,k]
// grid = (16 o-tiles, 16 k-slices) = 256 CTAs, block = 256.
// Each thread: 8 outputs (contiguous o group), 512 FMAs, broadcast W reads.
// ---------------------------------------------------------------------------
__global__ void __launch_bounds__(256) k3b_gemm(const float* __restrict__ h_t,
                                                const float* __restrict__ W_r) {
    __shared__ float cat_sh[64][68];   // [b][k], padded (16B-aligned rows)
    __shared__ float W_sh[32][68];     // [o_local][k]
    const int t = threadIdx.x;
    const int otile = blockIdx.x;
    const int ks    = blockIdx.y;
    const int kbase = ks * KSL;

    const float* src = (kbase < HH) ? (g_ct + kbase) : (h_t + (kbase - HH));
    for (int i = t; i < 64 * 16; i += 256) {          // 1024 float4
        const int bb = i >> 4, k4 = i & 15;
        const float4 v = *reinterpret_cast<const float4*>(src + bb * HH + k4 * 4);
        *reinterpret_cast<float4*>(&cat_sh[bb][k4 * 4]) = v;
    }
    for (int i = t; i < 32 * 16; i += 256) {          // 512 float4
        const int oo = i >> 4, k4 = i & 15;
        const float4 v = *reinterpret_cast<const float4*>(
            W_r + (size_t)(otile * 32 + oo) * (2 * HH) + kbase + k4 * 4);
        *reinterpret_cast<float4*>(&W_sh[oo][k4 * 4]) = v;
    }
    __syncthreads();

    const int b = t & 63, og = t >> 6;                // og: 0..3
    float acc[8];
#pragma unroll
    for (int j = 0; j < 8; j++) acc[j] = 0.f;

#pragma unroll
    for (int kk = 0; kk < 16; kk++) {
        const float4 c4 = *reinterpret_cast<const float4*>(&cat_sh[b][kk * 4]);
#pragma unroll
        for (int j = 0; j < 8; j++) {
            const float4 w4 =
                *reinterpret_cast<const float4*>(&W_sh[og * 8 + j][kk * 4]);
            acc[j] += c4.x * w4.x + c4.y * w4.y + c4.z * w4.z + c4.w * w4.w;
        }
    }
#pragma unroll
    for (int j = 0; j < 8; j++) {
        const int o = otile * 32 + og * 8 + j;
        g_opart[(size_t)ks * HH * BB + o * BB + b] = acc[j];   // coalesced in b
    }
}

// ---------------------------------------------------------------------------
// K3c: out[b,o] = tanh(b_r[o] + sum_ks opart[ks][o][b]); smem transpose write.
// grid = 64 CTAs (8 o each), block = 512.
// ---------------------------------------------------------------------------
__global__ void __launch_bounds__(512) k3c_fin(const float* __restrict__ b_r,
                                               float* __restrict__ out) {
    __shared__ float sh[8][65];
    const int c = blockIdx.x;
    const int t = threadIdx.x;
    const int j = t >> 6, b = t & 63;
    const int o = c * 8 + j;
    float s = 0.f;
#pragma unroll
    for (int ks = 0; ks < KS; ks++)
        s += g_opart[(size_t)ks * HH * BB + o * BB + b];
    sh[j][b] = tanhf(s + b_r[o]);
    __syncthreads();
    const int b2 = t >> 3, j2 = t & 7;
    out[b2 * HH + c * 8 + j2] = sh[j2][b2];
}

// ---------------------------------------------------------------------------
extern "C" void kernel_launch(void* const* d_in, const int* in_sizes, int n_in,
                              void* d_out, int out_size) {
    const float* hs   = (const float*)d_in[0];   // [S,B,H]
    const float* h_t  = (const float*)d_in[1];   // [B,H]
    const int*   mask = (const int*)  d_in[2];   // [B,S]
    const float* W_a  = (const float*)d_in[3];   // [H,H]
    // d_in[4] = b_a : cancels in softmax (per-b constant)
    const float* W_r  = (const float*)d_in[5];   // [H,2H]
    const float* b_r  = (const float*)d_in[6];   // [H]
    float* out = (float*)d_out;                  // [B,H]

    k1_proj<<<HH / 16, 512>>>(W_a, h_t);
    k2_flash<<<dim3(SPL, BB), 256>>>(hs, mask);
    k3a_combine<<<BB, 512>>>();
    k3b_gemm<<<dim3(16, KS), 256>>>(h_t, W_r);
    k3c_fin<<<BB, 512>>>(b_r, out);
}